// round 1
// baseline (speedup 1.0000x reference)
#include <cuda_runtime.h>
#include <cuda_bf16.h>

// Problem constants (match reference)
#define C_BINS 9
#define H_DIM 260
#define W_DIM 346
#define B_DIM 16
#define HID 100
#define NEG_SLOPE 0.1f

#define WH (W_DIM * H_DIM)            // 89960
#define WHC (W_DIM * H_DIM * C_BINS)  // 809640
#define WHC2 (2 * WHC)                // 1619280
#define NUM_VOX (WHC2 * B_DIM)        // 25908480

// Lookup table for the scalar->scalar ValueLayer MLP over t' in [-1, 1].
#define T_TAB 32768
__device__ float g_table[T_TAB];

__device__ __forceinline__ float lrelu(float v) {
    return v >= 0.0f ? v : NEG_SLOPE * v;
}

// ---------------------------------------------------------------------------
// Kernel 1: build the piecewise-linear lookup table by evaluating the MLP
// exactly at T_TAB points. W2 lives in shared memory (broadcast reads:
// all threads in a warp read the same (k,j) element for different t).
// h1[100] is fully unrolled -> registers.
// ---------------------------------------------------------------------------
__global__ __launch_bounds__(128) void build_table_kernel(
    const float* __restrict__ W1, const float* __restrict__ b1,
    const float* __restrict__ W2, const float* __restrict__ b2,
    const float* __restrict__ W3, const float* __restrict__ b3)
{
    __shared__ float sW2[HID * HID];
    __shared__ float sw1[HID], sb1[HID], sb2[HID], sw3[HID];
    __shared__ float sb3;

    const int tid = threadIdx.x;
    for (int i = tid; i < HID * HID; i += blockDim.x) sW2[i] = W2[i];
    if (tid < HID) {
        sw1[tid] = W1[tid];   // W1 is (HID,1) -> column 0
        sb1[tid] = b1[tid];
        sb2[tid] = b2[tid];
        sw3[tid] = W3[tid];   // W3 is (1,HID)
    }
    if (tid == 0) sb3 = b3[0];
    __syncthreads();

    const int idx = blockIdx.x * blockDim.x + tid;
    if (idx >= T_TAB) return;

    const float t = -1.0f + 2.0f * (float)idx / (float)(T_TAB - 1);

    // Layer 1: h1_j = lrelu(t * w1_j + b1_j)
    float h1[HID];
#pragma unroll
    for (int j = 0; j < HID; j++) {
        h1[j] = lrelu(fmaf(t, sw1[j], sb1[j]));
    }

    // Layer 2 + 3: out = b3 + sum_k w3_k * lrelu(b2_k + sum_j W2[k,j]*h1_j)
    float out = sb3;
    for (int k = 0; k < HID; k++) {
        float z = sb2[k];
        const float* w2row = &sW2[k * HID];
#pragma unroll
        for (int j = 0; j < HID; j++) {
            z = fmaf(w2row[j], h1[j], z);
        }
        out = fmaf(sw3[k], lrelu(z), out);
    }

    g_table[idx] = out;
}

// ---------------------------------------------------------------------------
// Kernel 2: scatter. For each event, one base index; for each of 9 bins,
// a linear-interp table lookup and an atomicAdd.
// Output flat layout [B, 2C, H, W] equals the raw voxel index
//   x + W*y + W*H*i + W*H*C*p + 2*W*H*C*b   (verified: concat(p=0, p=1)
//   along channel axis reproduces exactly this ordering).
// ---------------------------------------------------------------------------
__global__ __launch_bounds__(256) void scatter_kernel(
    const int* __restrict__ xs, const int* __restrict__ ys,
    const float* __restrict__ ts, const int* __restrict__ ps,
    const int* __restrict__ bs, float* __restrict__ out, int E)
{
    const int e = blockIdx.x * blockDim.x + threadIdx.x;
    if (e >= E) return;

    const float t = ts[e];
    const int base = xs[e] + W_DIM * ys[e] + WHC * ps[e] + WHC2 * bs[e];

    const float scale = (float)(T_TAB - 1) * 0.5f;

#pragma unroll
    for (int i = 0; i < C_BINS; i++) {
        const float tp = t - (float)i * 0.125f;   // i/(C-1), exact in binary
        float u = (tp + 1.0f) * scale;
        int i0 = (int)u;
        i0 = min(max(i0, 0), T_TAB - 2);
        const float fr = u - (float)i0;
        const float f0 = g_table[i0];
        const float f1 = g_table[i0 + 1];
        const float val = t * fmaf(fr, f1 - f0, f0);
        atomicAdd(&out[base + WH * i], val);
    }
}

// ---------------------------------------------------------------------------
// Launch
// Inputs (metadata order): xs, ys, ts, ps, bs, W1, b1, W2, b2, W3, b3
// ---------------------------------------------------------------------------
extern "C" void kernel_launch(void* const* d_in, const int* in_sizes, int n_in,
                              void* d_out, int out_size)
{
    const int*   xs = (const int*)d_in[0];
    const int*   ys = (const int*)d_in[1];
    const float* ts = (const float*)d_in[2];
    const int*   ps = (const int*)d_in[3];
    const int*   bs = (const int*)d_in[4];
    const float* W1 = (const float*)d_in[5];
    const float* b1 = (const float*)d_in[6];
    const float* W2 = (const float*)d_in[7];
    const float* b2 = (const float*)d_in[8];
    const float* W3 = (const float*)d_in[9];
    const float* b3 = (const float*)d_in[10];
    float* out = (float*)d_out;

    const int E = in_sizes[0];

    // Zero the voxel grid (output poisoned to 0xAA by harness).
    cudaMemsetAsync(out, 0, (size_t)out_size * sizeof(float), 0);

    // Build the MLP lookup table.
    build_table_kernel<<<(T_TAB + 127) / 128, 128>>>(W1, b1, W2, b2, W3, b3);

    // Scatter events into the voxel grid.
    scatter_kernel<<<(E + 255) / 256, 256>>>(xs, ys, ts, ps, bs, out, E);
}

// round 2
// speedup vs baseline: 1.1429x; 1.1429x over previous
#include <cuda_runtime.h>
#include <cuda_bf16.h>

// Problem constants (match reference)
#define C_BINS 9
#define H_DIM 260
#define W_DIM 346
#define HID 100
#define NEG_SLOPE 0.1f

#define WH (W_DIM * H_DIM)            // 89960
#define WHC (WH * C_BINS)             // 809640
#define WHC2 (2 * WHC)                // 1619280

// Lookup table: T' in [-1,1], TCELLS cells. TCELLS/16 = exact integer cell
// shift per temporal bin (bin spacing 1/8, half-range scale TCELLS/2).
#define TCELLS 4096
#define TENT   (TCELLS + 1)           // 4097 sample points
#define TSHIFT (TCELLS / 16)          // 256 cells per bin
#define TSCALE ((float)(TCELLS / 2))  // 2048.0f
#define TPAD   (TENT + 7)             // 4104, float4-friendly

__device__ __align__(16) float g_tab[TPAD];

__device__ __forceinline__ float lrelu(float v) {
    return v >= 0.0f ? v : NEG_SLOPE * v;
}

// ---------------------------------------------------------------------------
// Fused prep kernel.
//   blocks [0, TB_BLOCKS): build the MLP lookup table, warp-per-point,
//     k-dimension split across the 32 lanes (breaks the serial FMA chain).
//   blocks [TB_BLOCKS, grid): zero the voxel grid (grid-stride float4).
// ---------------------------------------------------------------------------
#define TB_BLOCKS 513   // 513 blocks * 8 warps >= 4097 points
#define ZB_BLOCKS 2048

__global__ __launch_bounds__(256) void prep_kernel(
    const float* __restrict__ W1, const float* __restrict__ b1,
    const float* __restrict__ W2, const float* __restrict__ b2,
    const float* __restrict__ W3, const float* __restrict__ b3,
    float* __restrict__ out, int out_n)
{
    if (blockIdx.x < TB_BLOCKS) {
        // ---- table build ----
        __shared__ float sW2[HID * 101];   // rows padded to 101 -> conflict-free LDS
        __shared__ float sw1[HID], sb1[HID], sb2[HID], sw3[HID];

        const int tid = threadIdx.x;
        for (int i = tid; i < HID * HID; i += 256) {
            const int k = i / HID;
            const int j = i - k * HID;
            sW2[k * 101 + j] = W2[i];
        }
        if (tid < HID) {
            sw1[tid] = W1[tid];
            sb1[tid] = b1[tid];
            sb2[tid] = b2[tid];
            sw3[tid] = W3[tid];
        }
        __syncthreads();

        const int warp = tid >> 5;
        const int lane = tid & 31;
        const int p = blockIdx.x * 8 + warp;
        if (p >= TENT) return;

        const float t = -1.0f + (float)p / TSCALE;

        // Layer 1 (replicated per lane, registers)
        float h1[HID];
#pragma unroll
        for (int j = 0; j < HID; j++) {
            h1[j] = lrelu(fmaf(t, sw1[j], sb1[j]));
        }

        // Layers 2+3, k split across lanes
        float part = 0.0f;
        for (int k = lane; k < HID; k += 32) {
            float z = sb2[k];
            const float* r = &sW2[k * 101];
#pragma unroll
            for (int j = 0; j < HID; j++) {
                z = fmaf(r[j], h1[j], z);
            }
            part = fmaf(sw3[k], lrelu(z), part);
        }
#pragma unroll
        for (int off = 16; off >= 1; off >>= 1) {
            part += __shfl_xor_sync(0xffffffffu, part, off);
        }
        if (lane == 0) g_tab[p] = part + b3[0];
    } else {
        // ---- zero the output ----
        const int zb = blockIdx.x - TB_BLOCKS;
        const int nthr = ZB_BLOCKS * 256;
        float4* o4 = (float4*)out;
        const int n4 = out_n >> 2;
        const float4 z4 = make_float4(0.f, 0.f, 0.f, 0.f);
        for (int i = zb * 256 + threadIdx.x; i < n4; i += nthr) {
            o4[i] = z4;
        }
        if (zb == 0 && threadIdx.x < (out_n & 3)) {
            out[(n4 << 2) + threadIdx.x] = 0.0f;
        }
    }
}

// ---------------------------------------------------------------------------
// Scatter: 2 events per thread (vector loads), table in shared memory,
// single (u, fr, i0) per event serves all 9 bins (shift = exactly 256 cells).
// ---------------------------------------------------------------------------
__global__ __launch_bounds__(256) void scatter_kernel(
    const int* __restrict__ xs, const int* __restrict__ ys,
    const float* __restrict__ ts, const int* __restrict__ ps,
    const int* __restrict__ bs, float* __restrict__ out, int E)
{
    __shared__ __align__(16) float st[TPAD];
    {
        const float4* g4 = (const float4*)g_tab;
        float4* s4 = (float4*)st;
        for (int i = threadIdx.x; i < TPAD / 4; i += 256) s4[i] = g4[i];
    }
    __syncthreads();

    const int gid = blockIdx.x * 256 + threadIdx.x;
    const int e0 = gid * 2;
    if (e0 >= E) return;

    if (e0 + 1 < E) {
        const int2   x2 = *(const int2*)(xs + e0);
        const int2   y2 = *(const int2*)(ys + e0);
        const float2 t2 = *(const float2*)(ts + e0);
        const int2   p2 = *(const int2*)(ps + e0);
        const int2   b2 = *(const int2*)(bs + e0);

#pragma unroll
        for (int ev = 0; ev < 2; ev++) {
            const float t = (ev == 0) ? t2.x : t2.y;
            const int   x = (ev == 0) ? x2.x : x2.y;
            const int   y = (ev == 0) ? y2.x : y2.y;
            const int   p = (ev == 0) ? p2.x : p2.y;
            const int   b = (ev == 0) ? b2.x : b2.y;

            const int base = x + W_DIM * y + WHC * p + WHC2 * b;
            const float u = fmaf(t, TSCALE, TSCALE);   // (t+1)*2048
            int i0 = (int)u;
            i0 = min(i0, TCELLS - 1);
            const float fr = u - (float)i0;

#pragma unroll
            for (int i = 0; i < C_BINS; i++) {
                const int idx = i0 - TSHIFT * i;
                const float f0 = st[idx];
                const float f1 = st[idx + 1];
                const float val = t * fmaf(fr, f1 - f0, f0);
                atomicAdd(&out[base + WH * i], val);
            }
        }
    } else {
        // odd tail event
        const float t = ts[e0];
        const int base = xs[e0] + W_DIM * ys[e0] + WHC * ps[e0] + WHC2 * bs[e0];
        const float u = fmaf(t, TSCALE, TSCALE);
        int i0 = (int)u;
        i0 = min(i0, TCELLS - 1);
        const float fr = u - (float)i0;
#pragma unroll
        for (int i = 0; i < C_BINS; i++) {
            const int idx = i0 - TSHIFT * i;
            const float f0 = st[idx];
            const float f1 = st[idx + 1];
            const float val = t * fmaf(fr, f1 - f0, f0);
            atomicAdd(&out[base + WH * i], val);
        }
    }
}

// ---------------------------------------------------------------------------
// Launch. Inputs: xs, ys, ts, ps, bs, W1, b1, W2, b2, W3, b3
// ---------------------------------------------------------------------------
extern "C" void kernel_launch(void* const* d_in, const int* in_sizes, int n_in,
                              void* d_out, int out_size)
{
    const int*   xs = (const int*)d_in[0];
    const int*   ys = (const int*)d_in[1];
    const float* ts = (const float*)d_in[2];
    const int*   ps = (const int*)d_in[3];
    const int*   bs = (const int*)d_in[4];
    const float* W1 = (const float*)d_in[5];
    const float* b1 = (const float*)d_in[6];
    const float* W2 = (const float*)d_in[7];
    const float* b2 = (const float*)d_in[8];
    const float* W3 = (const float*)d_in[9];
    const float* b3 = (const float*)d_in[10];
    float* out = (float*)d_out;

    const int E = in_sizes[0];

    prep_kernel<<<TB_BLOCKS + ZB_BLOCKS, 256>>>(W1, b1, W2, b2, W3, b3,
                                                out, out_size);

    const int threads = 256;
    const int per_block = threads * 2;
    const int blocks = (E + per_block - 1) / per_block;
    scatter_kernel<<<blocks, threads>>>(xs, ys, ts, ps, bs, out, E);
}

// round 3
// speedup vs baseline: 1.2322x; 1.0782x over previous
#include <cuda_runtime.h>
#include <cuda_bf16.h>

// Problem constants (match reference)
#define C_BINS 9
#define H_DIM 260
#define W_DIM 346
#define HID 100
#define NEG_SLOPE 0.1f

#define WH (W_DIM * H_DIM)            // 89960
#define WHC (WH * C_BINS)             // 809640
#define WHC2 (2 * WHC)                // 1619280

// Lookup table: t' in [-1,1], TCELLS cells. Bin spacing 1/8 = exactly
// TSHIFT=256 cells, so one (i0, fr) serves all 9 bins.
#define TCELLS 4096
#define TENT   (TCELLS + 1)
#define TSHIFT (TCELLS / 16)          // 256
#define TSCALE ((float)(TCELLS / 2))  // 2048.0f
#define TPAD   (TENT + 7)             // float4-friendly

__device__ __align__(16) float g_tab[TPAD];

__device__ __forceinline__ float lrelu(float v) {
    return v >= 0.0f ? v : NEG_SLOPE * v;
}

// ---------------------------------------------------------------------------
// Fused prep kernel: table build (warp-per-point, k split across lanes)
// + output zeroing (grid-stride float4).
// ---------------------------------------------------------------------------
#define TB_BLOCKS 513
#define ZB_BLOCKS 2048

__global__ __launch_bounds__(256) void prep_kernel(
    const float* __restrict__ W1, const float* __restrict__ b1,
    const float* __restrict__ W2, const float* __restrict__ b2,
    const float* __restrict__ W3, const float* __restrict__ b3,
    float* __restrict__ out, int out_n)
{
    if (blockIdx.x < TB_BLOCKS) {
        __shared__ float sW2[HID * 101];
        __shared__ float sw1[HID], sb1[HID], sb2[HID], sw3[HID];

        const int tid = threadIdx.x;
        for (int i = tid; i < HID * HID; i += 256) {
            const int k = i / HID;
            const int j = i - k * HID;
            sW2[k * 101 + j] = W2[i];
        }
        if (tid < HID) {
            sw1[tid] = W1[tid];
            sb1[tid] = b1[tid];
            sb2[tid] = b2[tid];
            sw3[tid] = W3[tid];
        }
        __syncthreads();

        const int warp = tid >> 5;
        const int lane = tid & 31;
        const int p = blockIdx.x * 8 + warp;
        if (p >= TENT) return;

        const float t = -1.0f + (float)p / TSCALE;

        float h1[HID];
#pragma unroll
        for (int j = 0; j < HID; j++) {
            h1[j] = lrelu(fmaf(t, sw1[j], sb1[j]));
        }

        float part = 0.0f;
        for (int k = lane; k < HID; k += 32) {
            float z = sb2[k];
            const float* r = &sW2[k * 101];
#pragma unroll
            for (int j = 0; j < HID; j++) {
                z = fmaf(r[j], h1[j], z);
            }
            part = fmaf(sw3[k], lrelu(z), part);
        }
#pragma unroll
        for (int off = 16; off >= 1; off >>= 1) {
            part += __shfl_xor_sync(0xffffffffu, part, off);
        }
        if (lane == 0) g_tab[p] = part + b3[0];
    } else {
        const int zb = blockIdx.x - TB_BLOCKS;
        const int nthr = ZB_BLOCKS * 256;
        float4* o4 = (float4*)out;
        const int n4 = out_n >> 2;
        const float4 z4 = make_float4(0.f, 0.f, 0.f, 0.f);
        for (int i = zb * 256 + threadIdx.x; i < n4; i += nthr) {
            o4[i] = z4;
        }
        if (zb == 0 && threadIdx.x < (out_n & 3)) {
            out[(n4 << 2) + threadIdx.x] = 0.0f;
        }
    }
}

// ---------------------------------------------------------------------------
// Persistent sliding-window scatter.
// Events are sorted by batch (bs = repeat(arange(16), 32768)); one batch's
// footprint is a contiguous 6.5 MB output slice. With only 296 resident
// blocks grid-striding in near-lockstep over event pairs, the concurrently
// active atomic working set is ~4-5 batches (~30 MB) -> L2-resident.
// ---------------------------------------------------------------------------
#define SCAT_BLOCKS 296
#define SCAT_THREADS 256
#define SCAT_STRIDE (SCAT_BLOCKS * SCAT_THREADS * 2)

__global__ __launch_bounds__(SCAT_THREADS) void scatter_kernel(
    const int* __restrict__ xs, const int* __restrict__ ys,
    const float* __restrict__ ts, const int* __restrict__ ps,
    const int* __restrict__ bs, float* __restrict__ out, int E)
{
    __shared__ __align__(16) float st[TPAD];
    {
        const float4* g4 = (const float4*)g_tab;
        float4* s4 = (float4*)st;
        for (int i = threadIdx.x; i < TPAD / 4; i += SCAT_THREADS) s4[i] = g4[i];
    }
    __syncthreads();

    const int start = (blockIdx.x * SCAT_THREADS + threadIdx.x) * 2;

    for (int e0 = start; e0 < E; e0 += SCAT_STRIDE) {
        if (e0 + 1 < E) {
            const int2   x2 = *(const int2*)(xs + e0);
            const int2   y2 = *(const int2*)(ys + e0);
            const float2 t2 = *(const float2*)(ts + e0);
            const int2   p2 = *(const int2*)(ps + e0);
            const int2   b2 = *(const int2*)(bs + e0);

#pragma unroll
            for (int ev = 0; ev < 2; ev++) {
                const float t = (ev == 0) ? t2.x : t2.y;
                const int   x = (ev == 0) ? x2.x : x2.y;
                const int   y = (ev == 0) ? y2.x : y2.y;
                const int   p = (ev == 0) ? p2.x : p2.y;
                const int   b = (ev == 0) ? b2.x : b2.y;

                const int base = x + W_DIM * y + WHC * p + WHC2 * b;
                const float u = fmaf(t, TSCALE, TSCALE);
                int i0 = (int)u;
                i0 = min(i0, TCELLS - 1);
                const float fr = u - (float)i0;

#pragma unroll
                for (int i = 0; i < C_BINS; i++) {
                    const int idx = i0 - TSHIFT * i;
                    const float f0 = st[idx];
                    const float f1 = st[idx + 1];
                    const float val = t * fmaf(fr, f1 - f0, f0);
                    atomicAdd(&out[base + WH * i], val);
                }
            }
        } else {
            const float t = ts[e0];
            const int base = xs[e0] + W_DIM * ys[e0] + WHC * ps[e0] + WHC2 * bs[e0];
            const float u = fmaf(t, TSCALE, TSCALE);
            int i0 = (int)u;
            i0 = min(i0, TCELLS - 1);
            const float fr = u - (float)i0;
#pragma unroll
            for (int i = 0; i < C_BINS; i++) {
                const int idx = i0 - TSHIFT * i;
                const float f0 = st[idx];
                const float f1 = st[idx + 1];
                const float val = t * fmaf(fr, f1 - f0, f0);
                atomicAdd(&out[base + WH * i], val);
            }
        }
    }
}

// ---------------------------------------------------------------------------
// Launch. Inputs: xs, ys, ts, ps, bs, W1, b1, W2, b2, W3, b3
// ---------------------------------------------------------------------------
extern "C" void kernel_launch(void* const* d_in, const int* in_sizes, int n_in,
                              void* d_out, int out_size)
{
    const int*   xs = (const int*)d_in[0];
    const int*   ys = (const int*)d_in[1];
    const float* ts = (const float*)d_in[2];
    const int*   ps = (const int*)d_in[3];
    const int*   bs = (const int*)d_in[4];
    const float* W1 = (const float*)d_in[5];
    const float* b1 = (const float*)d_in[6];
    const float* W2 = (const float*)d_in[7];
    const float* b2 = (const float*)d_in[8];
    const float* W3 = (const float*)d_in[9];
    const float* b3 = (const float*)d_in[10];
    float* out = (float*)d_out;

    const int E = in_sizes[0];

    prep_kernel<<<TB_BLOCKS + ZB_BLOCKS, 256>>>(W1, b1, W2, b2, W3, b3,
                                                out, out_size);

    scatter_kernel<<<SCAT_BLOCKS, SCAT_THREADS>>>(xs, ys, ts, ps, bs, out, E);
}